// round 9
// baseline (speedup 1.0000x reference)
#include <cuda_runtime.h>

// ----------------------------------------------------------------------------
// Complex Daubechies wavelet forward decomposition, 6 levels. Round 9:
//  - software pipeline WITHOUT streams: 3 image-groups; each launch is the
//    union of independent (level, group) pieces dispatched by blockIdx range.
//    Small levels of earlier groups hide under later groups' level-0 work.
//  - one 'mega' kernel: wave levels 0..3 (runtime-sized tile kernel, FFMA-imm
//    coefficients) + fused levels 4..5 tail piece (256-thread variant).
//  - per-level scratch buffers (disjoint across concurrently-running levels).
// ----------------------------------------------------------------------------

#define C_LR0 (-0.046875f)
#define C_LR1 ( 0.078125f)
#define C_LR2 ( 0.46875f)
#define C_LI0 (-0.0605153648f)
#define C_LI1 (-0.0605153648f)
#define C_LI2 ( 0.1210307296f)
#define C_HR0 (-0.046875f)
#define C_HR1 (-0.078125f)
#define C_HR2 ( 0.46875f)
#define C_HI0 ( 0.0605153648f)
#define C_HI1 (-0.0605153648f)
#define C_HI2 (-0.1210307296f)

#define DECL_COEFS \
    const float KLR[3] = {C_LR0, C_LR1, C_LR2}; \
    const float KLI[3] = {C_LI0, C_LI1, C_LI2}; \
    const float KHR[3] = {C_HR0, C_HR1, C_HR2}; \
    const float KHI[3] = {C_HI0, C_HI1, C_HI2};

// Per-level scratch (disjoint; safe across concurrent pieces).
__device__ float g_s01[24u * 2u * 512u * 512u];
__device__ float g_s12[24u * 2u * 256u * 256u];
__device__ float g_s23[24u * 2u * 128u * 128u];
__device__ float g_s34[24u * 2u * 64u * 64u];

struct Plan {
    int n;
    int bid_end[4];
    int level[4];   // 0..3 = wave level, 4 = fused tail (levels 4..5)
    int img0[4];
};

// Tile constants for wave pieces.
#define TRW 16
#define TCW 32
#define RIW 36        // 2*TRW + 4
#define PW  36        // TCW + 4
#define SARR 1296     // RIW * PW

// ------------------------- tail (levels 4..5) helpers -----------------------
__device__ __forceinline__ void tail_level(
    const float* sre, const float* sim, int ps,
    float* dre, float* dim, int pd,
    float* I0, float* I1, float* I2, float* I3,
    float* o_re, float* o_im, int h, bool last, int tid)
{
    DECL_COEFS
    const int hm = h - 1, W = h + 5, half = h >> 1;
    for (int s0 = 0; s0 < half; s0 += 8) {
        for (int idx = tid; idx < 8 * W; idx += 256) {
            int rr = idx / W, jx = idx - rr * W;
            int col = (jx - 3) & hm;
            int r2 = 2 * (s0 + rr) - 3;
            float aLr = 0, aLi = 0, aHr = 0, aHi = 0;
            #pragma unroll
            for (int t = 0; t < 3; t++) {
                int ra = (r2 + t) & hm, rb = (r2 + 5 - t) & hm;
                float xa = sre[ra * ps + col], xb = sre[rb * ps + col];
                float va = sim[ra * ps + col], vb = sim[rb * ps + col];
                float p = xa + xb, m = xa - xb, q = va + vb, n = va - vb;
                aLr += KLR[t]*p;  aLr -= KLI[t]*q;
                aLi += KLI[t]*p;  aLi += KLR[t]*q;
                aHr += KHR[t]*m;  aHr -= KHI[t]*n;
                aHi += KHI[t]*m;  aHi += KHR[t]*n;
            }
            I0[rr * 136 + jx] = aLr; I1[rr * 136 + jx] = aLi;
            I2[rr * 136 + jx] = aHr; I3[rr * 136 + jx] = aHi;
        }
        __syncthreads();
        for (int idx = tid; idx < 8 * half; idx += 256) {
            int rr = idx / half, c = idx - rr * half;
            int r = s0 + rr;
            float LLr = 0, LLi = 0, LHr = 0, LHi = 0;
            float HLr = 0, HLi = 0, HHr = 0, HHi = 0;
            #pragma unroll
            for (int t = 0; t < 3; t++) {
                int j0 = 2 * c + t, j1 = 2 * c + 5 - t;
                float ar = I0[rr * 136 + j0], br = I0[rr * 136 + j1];
                float ai = I1[rr * 136 + j0], bi = I1[rr * 136 + j1];
                float p = ar + br, m = ar - br, q = ai + bi, n = ai - bi;
                LLr += KLR[t]*p;  LLr -= KLI[t]*q;
                LLi += KLI[t]*p;  LLi += KLR[t]*q;
                LHr += KHR[t]*m;  LHr -= KHI[t]*n;
                LHi += KHI[t]*m;  LHi += KHR[t]*n;
                ar = I2[rr * 136 + j0]; br = I2[rr * 136 + j1];
                ai = I3[rr * 136 + j0]; bi = I3[rr * 136 + j1];
                p = ar + br; m = ar - br; q = ai + bi; n = ai - bi;
                HLr += KLR[t]*p;  HLr -= KLI[t]*q;
                HLi += KLI[t]*p;  HLi += KLR[t]*q;
                HHr += KHR[t]*m;  HHr -= KHI[t]*n;
                HHi += KHI[t]*m;  HHi += KHR[t]*n;
            }
            o_re[r * 1024 + c + half]          = LHr;
            o_im[r * 1024 + c + half]          = LHi;
            o_re[(r + half) * 1024 + c]        = HLr;
            o_im[(r + half) * 1024 + c]        = HLi;
            o_re[(r + half) * 1024 + c + half] = HHr;
            o_im[(r + half) * 1024 + c + half] = HHi;
            if (last) {
                o_re[r * 1024 + c] = LLr;
                o_im[r * 1024 + c] = LLi;
            } else {
                dre[r * pd + c] = LLr;
                dim[r * pd + c] = LLi;
            }
        }
        __syncthreads();
    }
}

// ------------------------------- mega kernel --------------------------------
__global__ void __launch_bounds__(256)
mega(const float* __restrict__ images, float* __restrict__ out,
     float* __restrict__ s01, float* __restrict__ s12,
     float* __restrict__ s23, float* __restrict__ s34, Plan plan)
{
    extern __shared__ float sm[];
    DECL_COEFS

    const int tid = threadIdx.x;
    const int bid = blockIdx.x;
    int pi = 0;
    if (bid >= plan.bid_end[0]) pi = 1;
    if (pi == 1 && bid >= plan.bid_end[1]) pi = 2;
    if (pi == 2 && bid >= plan.bid_end[2]) pi = 3;
    const int rel   = bid - (pi == 0 ? 0 : plan.bid_end[pi - 1]);
    const int level = plan.level[pi];

    if (level < 4) {
        // =========================== wave piece ============================
        const int h = 1024 >> level, half = h >> 1, hm = h - 1;
        const int tx  = half >> 5;               // half / TCW
        const int per = tx * (half >> 4);        // * half / TRW
        const int imgr = rel / per;
        const int rr2  = rel - imgr * per;
        const int by = rr2 / tx;
        const int bx = rr2 - by * tx;
        const int img = plan.img0[pi] + imgr;
        const int r0 = by * TRW, c0 = bx * TCW;

        const float* in_re; const float* in_im; int irs;
        float* nxt;
        if (level == 0)      { in_re = images + (long)img * 1048576; in_im = in_re; irs = 1024; nxt = s01; }
        else if (level == 1) { in_re = s01 + (long)img * 2l * 512 * 512; in_im = in_re + 512 * 512; irs = 512; nxt = s12; }
        else if (level == 2) { in_re = s12 + (long)img * 2l * 256 * 256; in_im = in_re + 256 * 256; irs = 256; nxt = s23; }
        else                 { in_re = s23 + (long)img * 2l * 128 * 128; in_im = in_re + 128 * 128; irs = 128; nxt = s34; }

        float* S0 = sm;
        float* S1 = sm + SARR;
        float* S2 = sm + 2 * SARR;
        float* S3 = sm + 3 * SARR;

        // ---- Phase A: W-direction conv, registers -> smem ----
        const int gr0  = 2 * r0 - 3;
        const int gcal = 2 * c0 - 4;
        if (level == 0) {
            for (int idx = tid; idx < RIW * (TCW / 4); idx += 256) {
                int ri = idx >> 3;           // / 8
                int j  = idx & 7;
                int gr = (gr0 + ri) & hm;
                const float* pr = in_re + (long)gr * irs;
                float x[16];
                #pragma unroll
                for (int k = 0; k < 4; k++) {
                    int gc = (gcal + 8 * j + 4 * k) & hm;
                    float4 v = __ldcs((const float4*)(pr + gc));
                    x[4*k] = v.x; x[4*k+1] = v.y; x[4*k+2] = v.z; x[4*k+3] = v.w;
                }
                float lre[4], lim[4], hre[4], him[4];
                #pragma unroll
                for (int c = 0; c < 4; c++) {
                    float a = 0.f, b = 0.f, d = 0.f, e = 0.f;
                    #pragma unroll
                    for (int t = 0; t < 3; t++) {
                        float xt = x[2*c + 1 + t], xs = x[2*c + 6 - t];
                        float p = xt + xs, m = xt - xs;
                        a += KLR[t] * p;  b += KLI[t] * p;
                        d += KHR[t] * m;  e += KHI[t] * m;
                    }
                    lre[c] = a; lim[c] = b; hre[c] = d; him[c] = e;
                }
                int o = ri * PW + 4 * j;
                *(float4*)&S0[o] = make_float4(lre[0], lre[1], lre[2], lre[3]);
                *(float4*)&S1[o] = make_float4(lim[0], lim[1], lim[2], lim[3]);
                *(float4*)&S2[o] = make_float4(hre[0], hre[1], hre[2], hre[3]);
                *(float4*)&S3[o] = make_float4(him[0], him[1], him[2], him[3]);
            }
        } else {
            for (int idx = tid; idx < RIW * (TCW / 4); idx += 256) {
                int ri = idx >> 3;
                int j  = idx & 7;
                int gr = (gr0 + ri) & hm;
                const float* pr = in_re + (long)gr * irs;
                const float* pyi = in_im + (long)gr * irs;
                float x[16], y[16];
                #pragma unroll
                for (int k = 0; k < 4; k++) {
                    int gc = (gcal + 8 * j + 4 * k) & hm;
                    float4 v = *(const float4*)(pr + gc);
                    x[4*k] = v.x; x[4*k+1] = v.y; x[4*k+2] = v.z; x[4*k+3] = v.w;
                    float4 w = *(const float4*)(pyi + gc);
                    y[4*k] = w.x; y[4*k+1] = w.y; y[4*k+2] = w.z; y[4*k+3] = w.w;
                }
                float lre[4], lim[4], hre[4], him[4];
                #pragma unroll
                for (int c = 0; c < 4; c++) {
                    float a = 0.f, b = 0.f, d = 0.f, e = 0.f;
                    #pragma unroll
                    for (int t = 0; t < 3; t++) {
                        float xt = x[2*c + 1 + t], xs = x[2*c + 6 - t];
                        float p = xt + xs, m = xt - xs;
                        a += KLR[t] * p;  b += KLI[t] * p;
                        d += KHR[t] * m;  e += KHI[t] * m;
                        float yt = y[2*c + 1 + t], ys = y[2*c + 6 - t];
                        float q = yt + ys, n = yt - ys;
                        a -= KLI[t] * q;  b += KLR[t] * q;
                        d -= KHI[t] * n;  e += KHR[t] * n;
                    }
                    lre[c] = a; lim[c] = b; hre[c] = d; him[c] = e;
                }
                int o = ri * PW + 4 * j;
                *(float4*)&S0[o] = make_float4(lre[0], lre[1], lre[2], lre[3]);
                *(float4*)&S1[o] = make_float4(lim[0], lim[1], lim[2], lim[3]);
                *(float4*)&S2[o] = make_float4(hre[0], hre[1], hre[2], hre[3]);
                *(float4*)&S3[o] = make_float4(him[0], him[1], him[2], him[3]);
            }
        }
        __syncthreads();

        // ---- Phase B: H-direction conv -> 4 quadrants ----
        float* o_re = out + (long)img * (2l * 1024 * 1024);
        float* o_im = o_re + 1024 * 1024;
        float* n_re = nxt + (long)img * 2l * half * half;
        float* n_im = n_re + (long)half * half;

        {
            int idx = tid;                      // exactly TRW*TCW/2 = 256 items
            int r  = idx >> 4;                  // / (TCW/2)
            int cg = idx & 15;
            int c2 = 2 * cg;
            float LLr0=0, LLi0=0, LHr0=0, LHi0=0, HLr0=0, HLi0=0, HHr0=0, HHi0=0;
            float LLr1=0, LLi1=0, LHr1=0, LHi1=0, HLr1=0, HLi1=0, HHr1=0, HHi1=0;
            #pragma unroll
            for (int t = 0; t < 3; t++) {
                int ra = (2 * r + t) * PW + c2;
                int rb = (2 * r + 5 - t) * PW + c2;
                float2 art = *(const float2*)&S0[ra], ars = *(const float2*)&S0[rb];
                float2 ait = *(const float2*)&S1[ra], ais = *(const float2*)&S1[rb];
                float2 brt = *(const float2*)&S2[ra], brs = *(const float2*)&S2[rb];
                float2 bit = *(const float2*)&S3[ra], bis = *(const float2*)&S3[rb];
                {
                    float p = art.x + ars.x, m = art.x - ars.x;
                    float q = ait.x + ais.x, n = ait.x - ais.x;
                    LLr0 += KLR[t]*p;  LLr0 -= KLI[t]*q;
                    LLi0 += KLI[t]*p;  LLi0 += KLR[t]*q;
                    HLr0 += KHR[t]*m;  HLr0 -= KHI[t]*n;
                    HLi0 += KHI[t]*m;  HLi0 += KHR[t]*n;
                    float p2 = brt.x + brs.x, m2 = brt.x - brs.x;
                    float q2 = bit.x + bis.x, n2 = bit.x - bis.x;
                    LHr0 += KLR[t]*p2; LHr0 -= KLI[t]*q2;
                    LHi0 += KLI[t]*p2; LHi0 += KLR[t]*q2;
                    HHr0 += KHR[t]*m2; HHr0 -= KHI[t]*n2;
                    HHi0 += KHI[t]*m2; HHi0 += KHR[t]*n2;
                }
                {
                    float p = art.y + ars.y, m = art.y - ars.y;
                    float q = ait.y + ais.y, n = ait.y - ais.y;
                    LLr1 += KLR[t]*p;  LLr1 -= KLI[t]*q;
                    LLi1 += KLI[t]*p;  LLi1 += KLR[t]*q;
                    HLr1 += KHR[t]*m;  HLr1 -= KHI[t]*n;
                    HLi1 += KHI[t]*m;  HLi1 += KHR[t]*n;
                    float p2 = brt.y + brs.y, m2 = brt.y - brs.y;
                    float q2 = bit.y + bis.y, n2 = bit.y - bis.y;
                    LHr1 += KLR[t]*p2; LHr1 -= KLI[t]*q2;
                    LHi1 += KLI[t]*p2; LHi1 += KLR[t]*q2;
                    HHr1 += KHR[t]*m2; HHr1 -= KHI[t]*n2;
                    HHi1 += KHI[t]*m2; HHi1 += KHR[t]*n2;
                }
            }
            int rl = r0 + r, rh = rl + half;
            int cl = c0 + c2, ch = cl + half;
            *(float2*)(n_re + (long)rl * half + cl) = make_float2(LLr0, LLr1);
            *(float2*)(n_im + (long)rl * half + cl) = make_float2(LLi0, LLi1);
            __stcs((float2*)(o_re + (long)rl * 1024 + ch), make_float2(LHr0, LHr1));
            __stcs((float2*)(o_im + (long)rl * 1024 + ch), make_float2(LHi0, LHi1));
            __stcs((float2*)(o_re + (long)rh * 1024 + cl), make_float2(HLr0, HLr1));
            __stcs((float2*)(o_im + (long)rh * 1024 + cl), make_float2(HLi0, HLi1));
            __stcs((float2*)(o_re + (long)rh * 1024 + ch), make_float2(HHr0, HHr1));
            __stcs((float2*)(o_im + (long)rh * 1024 + ch), make_float2(HHi0, HHi1));
        }
    } else {
        // =========================== tail piece ============================
        const int img = plan.img0[pi] + rel;
        const int AP = 68, BP = 36;
        float* A_re = sm;
        float* A_im = A_re + 64 * AP;
        float* B_re = A_im + 64 * AP;
        float* B_im = B_re + 32 * BP;
        float* I0   = B_im + 32 * BP;
        float* I1   = I0 + 8 * 136;
        float* I2   = I1 + 8 * 136;
        float* I3   = I2 + 8 * 136;

        const float* g_re = s34 + (long)img * 2l * 64 * 64;
        const float* g_im = g_re + 64 * 64;
        for (int idx = tid; idx < 64 * 16; idx += 256) {
            int rr = idx >> 4, c4 = (idx & 15) * 4;
            *(float4*)&A_re[rr * AP + c4] = *(const float4*)(g_re + rr * 64 + c4);
            *(float4*)&A_im[rr * AP + c4] = *(const float4*)(g_im + rr * 64 + c4);
        }
        __syncthreads();

        float* o_re = out + (long)img * 2l * 1024 * 1024;
        float* o_im = o_re + 1024 * 1024;

        tail_level(A_re, A_im, AP, B_re, B_im, BP, I0, I1, I2, I3,
                   o_re, o_im, 64, false, tid);
        tail_level(B_re, B_im, BP, nullptr, nullptr, 0, I0, I1, I2, I3,
                   o_re, o_im, 32, true, tid);
    }
}

// ================================= launch ===================================
extern "C" void kernel_launch(void* const* d_in, const int* in_sizes, int n_in,
                              void* d_out, int out_size) {
    const float* images = (const float*)d_in[0];
    float* out = (float*)d_out;

    float *s01, *s12, *s23, *s34;
    cudaGetSymbolAddress((void**)&s01, g_s01);
    cudaGetSymbolAddress((void**)&s12, g_s12);
    cudaGetSymbolAddress((void**)&s23, g_s23);
    cudaGetSymbolAddress((void**)&s34, g_s34);

    const int NG = 3, GS = 8;                       // 3 groups x 8 images
    // blocks per group at each pipeline stage (levels 0..3 wave, 4 = tail)
    const int blk_per_grp[5] = {512 * GS, 128 * GS, 32 * GS, 8 * GS, GS};

    constexpr size_t SMEM_WAVE = 4u * SARR * 4u;        // 20,736 B
    constexpr size_t SMEM_TAIL = 15360u * 4u;           // 61,440 B
    cudaFuncSetAttribute(mega, cudaFuncAttributeMaxDynamicSharedMemorySize,
                         SMEM_TAIL);

    for (int round = 0; round < NG + 4; round++) {
        Plan p; p.n = 0;
        int cum = 0;
        bool has_tail = false;
        for (int L = 0; L <= 4; L++) {
            int g = round - L;
            if (g < 0 || g >= NG) continue;
            cum += blk_per_grp[L];
            p.bid_end[p.n] = cum;
            p.level[p.n]   = L;
            p.img0[p.n]    = g * GS;
            if (L == 4) has_tail = true;
            p.n++;
        }
        for (int i = p.n; i < 4; i++) {
            p.bid_end[i] = 1 << 30; p.level[i] = 0; p.img0[i] = 0;
        }
        if (cum == 0) continue;
        size_t smem = has_tail ? SMEM_TAIL : SMEM_WAVE;
        mega<<<cum, 256, smem>>>(images, out, s01, s12, s23, s34, p);
    }
}

// round 10
// speedup vs baseline: 1.5332x; 1.5332x over previous
#include <cuda_runtime.h>

// ----------------------------------------------------------------------------
// Complex Daubechies wavelet forward decomposition, 6 levels. Round 10:
//  - ONE persistent kernel; levels separated by software grid barriers
//    (atomic count + generation spin). Grid sized by occupancy API so all
//    blocks are co-resident (no deadlock).
//  - per-level bodies are compile-time specialized templates (constexpr H,
//    TC=64 tiles, FFMA-immediate coefficients) — the thing R9 lost.
//  - scratch reads via __ldcg (L2; cross-block coherent). Detail stores __stcs.
// ----------------------------------------------------------------------------

#define C_LR0 (-0.046875f)
#define C_LR1 ( 0.078125f)
#define C_LR2 ( 0.46875f)
#define C_LI0 (-0.0605153648f)
#define C_LI1 (-0.0605153648f)
#define C_LI2 ( 0.1210307296f)
#define C_HR0 (-0.046875f)
#define C_HR1 (-0.078125f)
#define C_HR2 ( 0.46875f)
#define C_HI0 ( 0.0605153648f)
#define C_HI1 (-0.0605153648f)
#define C_HI2 (-0.1210307296f)

#define DECL_COEFS \
    const float KLR[3] = {C_LR0, C_LR1, C_LR2}; \
    const float KLI[3] = {C_LI0, C_LI1, C_LI2}; \
    const float KHR[3] = {C_HR0, C_HR1, C_HR2}; \
    const float KHI[3] = {C_HI0, C_HI1, C_HI2};

// Per-level scratch (distinct buffers: cross-block L1-staleness impossible).
__device__ float g_s01[24u * 2u * 512u * 512u];
__device__ float g_s12[24u * 2u * 256u * 256u];
__device__ float g_s23[24u * 2u * 128u * 128u];
__device__ float g_s34[24u * 2u * 64u * 64u];

// Grid-barrier state (generation scheme; persists safely across replays).
__device__ unsigned g_count = 0;
__device__ unsigned g_gen   = 0;

__device__ __forceinline__ void grid_barrier(unsigned nb) {
    __syncthreads();
    if (threadIdx.x == 0) {
        volatile unsigned* vgen = &g_gen;
        unsigned g = *vgen;
        __threadfence();
        unsigned old = atomicAdd(&g_count, 1);
        if (old == nb - 1) {
            g_count = 0;
            __threadfence();
            *vgen = g + 1;
        } else {
            while (*vgen == g) { }
        }
    }
    __syncthreads();
}

// Wave tile: TR=16, TC=64. RI=36 rows, smem pitch P=68. 512 threads.
#define TRW 16
#define TCW 64
#define RIW 36
#define PW  68
#define SARR 2448            // RIW * PW

template<int H, bool HAS_IM, bool STREAM_IN>
__device__ __forceinline__ void wave_tile(
    int u, const float* __restrict__ inb, float* __restrict__ out,
    float* __restrict__ nxt,
    float* S0, float* S1, float* S2, float* S3, int tid)
{
    DECL_COEFS
    constexpr int  half = H / 2;
    constexpr int  hm   = H - 1;
    constexpr int  TX   = half / TCW;
    constexpr int  TY   = half / TRW;
    constexpr int  TPI  = TX * TY;
    constexpr long ISTR = (long)(HAS_IM ? 2 : 1) * H * H;
    constexpr long CSTR = (long)H * H;

    const int img = u / TPI;
    const int rem = u - img * TPI;
    const int by  = rem / TX;
    const int bx  = rem - by * TX;
    const int r0  = by * TRW, c0 = bx * TCW;

    const float* in_re = inb + (long)img * ISTR;
    const float* in_im = in_re + CSTR;

    // ---- Phase A: W-direction conv, registers -> smem ----
    const int gr0  = 2 * r0 - 3;
    const int gcal = 2 * c0 - 4;
    for (int idx = tid; idx < RIW * (TCW / 4); idx += 512) {
        int ri = idx >> 4;
        int j  = idx & 15;
        int gr = (gr0 + ri) & hm;
        const float* pr = in_re + (long)gr * H;
        const float* pi = in_im + (long)gr * H;
        float x[16], y[16];
        #pragma unroll
        for (int k = 0; k < 4; k++) {
            int gc = (gcal + 8 * j + 4 * k) & hm;
            float4 v = STREAM_IN ? __ldcs((const float4*)(pr + gc))
                                 : __ldcg((const float4*)(pr + gc));
            x[4*k] = v.x; x[4*k+1] = v.y; x[4*k+2] = v.z; x[4*k+3] = v.w;
            if (HAS_IM) {
                float4 w = __ldcg((const float4*)(pi + gc));
                y[4*k] = w.x; y[4*k+1] = w.y; y[4*k+2] = w.z; y[4*k+3] = w.w;
            }
        }
        float lre[4], lim[4], hre[4], him[4];
        #pragma unroll
        for (int c = 0; c < 4; c++) {
            float a = 0.f, b = 0.f, d = 0.f, e = 0.f;
            #pragma unroll
            for (int t = 0; t < 3; t++) {
                float xt = x[2*c + 1 + t], xs = x[2*c + 6 - t];
                float p = xt + xs, m = xt - xs;
                a += KLR[t] * p;  b += KLI[t] * p;
                d += KHR[t] * m;  e += KHI[t] * m;
                if (HAS_IM) {
                    float yt = y[2*c + 1 + t], ys = y[2*c + 6 - t];
                    float q = yt + ys, n = yt - ys;
                    a -= KLI[t] * q;  b += KLR[t] * q;
                    d -= KHI[t] * n;  e += KHR[t] * n;
                }
            }
            lre[c] = a; lim[c] = b; hre[c] = d; him[c] = e;
        }
        int o = ri * PW + 4 * j;
        *(float4*)&S0[o] = make_float4(lre[0], lre[1], lre[2], lre[3]);
        *(float4*)&S1[o] = make_float4(lim[0], lim[1], lim[2], lim[3]);
        *(float4*)&S2[o] = make_float4(hre[0], hre[1], hre[2], hre[3]);
        *(float4*)&S3[o] = make_float4(him[0], him[1], him[2], him[3]);
    }
    __syncthreads();

    // ---- Phase B: H-direction conv -> 4 quadrants (one item per thread) ----
    float* o_re = out + (long)img * (2l * 1024 * 1024);
    float* o_im = o_re + 1024 * 1024;
    float* n_re = nxt + (long)img * 2l * half * half;
    float* n_im = n_re + (long)half * half;
    {
        int idx = tid;                   // TRW*TCW/2 = 512 items exactly
        int r  = idx >> 5;
        int cg = idx & 31;
        int c2 = 2 * cg;
        float LLr0=0, LLi0=0, LHr0=0, LHi0=0, HLr0=0, HLi0=0, HHr0=0, HHi0=0;
        float LLr1=0, LLi1=0, LHr1=0, LHi1=0, HLr1=0, HLi1=0, HHr1=0, HHi1=0;
        #pragma unroll
        for (int t = 0; t < 3; t++) {
            int ra = (2 * r + t) * PW + c2;
            int rb = (2 * r + 5 - t) * PW + c2;
            float2 art = *(const float2*)&S0[ra], ars = *(const float2*)&S0[rb];
            float2 ait = *(const float2*)&S1[ra], ais = *(const float2*)&S1[rb];
            float2 brt = *(const float2*)&S2[ra], brs = *(const float2*)&S2[rb];
            float2 bit = *(const float2*)&S3[ra], bis = *(const float2*)&S3[rb];
            {
                float p = art.x + ars.x, m = art.x - ars.x;
                float q = ait.x + ais.x, n = ait.x - ais.x;
                LLr0 += KLR[t]*p;  LLr0 -= KLI[t]*q;
                LLi0 += KLI[t]*p;  LLi0 += KLR[t]*q;
                HLr0 += KHR[t]*m;  HLr0 -= KHI[t]*n;
                HLi0 += KHI[t]*m;  HLi0 += KHR[t]*n;
                float p2 = brt.x + brs.x, m2 = brt.x - brs.x;
                float q2 = bit.x + bis.x, n2 = bit.x - bis.x;
                LHr0 += KLR[t]*p2; LHr0 -= KLI[t]*q2;
                LHi0 += KLI[t]*p2; LHi0 += KLR[t]*q2;
                HHr0 += KHR[t]*m2; HHr0 -= KHI[t]*n2;
                HHi0 += KHI[t]*m2; HHi0 += KHR[t]*n2;
            }
            {
                float p = art.y + ars.y, m = art.y - ars.y;
                float q = ait.y + ais.y, n = ait.y - ais.y;
                LLr1 += KLR[t]*p;  LLr1 -= KLI[t]*q;
                LLi1 += KLI[t]*p;  LLi1 += KLR[t]*q;
                HLr1 += KHR[t]*m;  HLr1 -= KHI[t]*n;
                HLi1 += KHI[t]*m;  HLi1 += KHR[t]*n;
                float p2 = brt.y + brs.y, m2 = brt.y - brs.y;
                float q2 = bit.y + bis.y, n2 = bit.y - bis.y;
                LHr1 += KLR[t]*p2; LHr1 -= KLI[t]*q2;
                LHi1 += KLI[t]*p2; LHi1 += KLR[t]*q2;
                HHr1 += KHR[t]*m2; HHr1 -= KHI[t]*n2;
                HHi1 += KHI[t]*m2; HHi1 += KHR[t]*n2;
            }
        }
        int rl = r0 + r, rh = rl + half;
        int cl = c0 + c2, ch = cl + half;
        *(float2*)(n_re + (long)rl * half + cl) = make_float2(LLr0, LLr1);
        *(float2*)(n_im + (long)rl * half + cl) = make_float2(LLi0, LLi1);
        __stcs((float2*)(o_re + (long)rl * 1024 + ch), make_float2(LHr0, LHr1));
        __stcs((float2*)(o_im + (long)rl * 1024 + ch), make_float2(LHi0, LHi1));
        __stcs((float2*)(o_re + (long)rh * 1024 + cl), make_float2(HLr0, HLr1));
        __stcs((float2*)(o_im + (long)rh * 1024 + cl), make_float2(HLi0, HLi1));
        __stcs((float2*)(o_re + (long)rh * 1024 + ch), make_float2(HHr0, HHr1));
        __stcs((float2*)(o_im + (long)rh * 1024 + ch), make_float2(HHi0, HHi1));
    }
    __syncthreads();   // S0..S3 reused by next tile iteration
}

// ----------------------------- tail (levels 4..5) ---------------------------
__device__ __forceinline__ void tail_level(
    const float* sre, const float* sim, int ps,
    float* dre, float* dim, int pd,
    float* I0, float* I1, float* I2, float* I3,
    float* o_re, float* o_im, int h, bool last, int tid)
{
    DECL_COEFS
    const int hm = h - 1, W = h + 5, half = h >> 1;
    for (int s0 = 0; s0 < half; s0 += 8) {
        for (int idx = tid; idx < 8 * W; idx += 512) {
            int rr = idx / W, jx = idx - rr * W;
            int col = (jx - 3) & hm;
            int r2 = 2 * (s0 + rr) - 3;
            float aLr = 0, aLi = 0, aHr = 0, aHi = 0;
            #pragma unroll
            for (int t = 0; t < 3; t++) {
                int ra = (r2 + t) & hm, rb = (r2 + 5 - t) & hm;
                float xa = sre[ra * ps + col], xb = sre[rb * ps + col];
                float va = sim[ra * ps + col], vb = sim[rb * ps + col];
                float p = xa + xb, m = xa - xb, q = va + vb, n = va - vb;
                aLr += KLR[t]*p;  aLr -= KLI[t]*q;
                aLi += KLI[t]*p;  aLi += KLR[t]*q;
                aHr += KHR[t]*m;  aHr -= KHI[t]*n;
                aHi += KHI[t]*m;  aHi += KHR[t]*n;
            }
            I0[rr * 136 + jx] = aLr; I1[rr * 136 + jx] = aLi;
            I2[rr * 136 + jx] = aHr; I3[rr * 136 + jx] = aHi;
        }
        __syncthreads();
        for (int idx = tid; idx < 8 * half; idx += 512) {
            int rr = idx / half, c = idx - rr * half;
            int r = s0 + rr;
            float LLr = 0, LLi = 0, LHr = 0, LHi = 0;
            float HLr = 0, HLi = 0, HHr = 0, HHi = 0;
            #pragma unroll
            for (int t = 0; t < 3; t++) {
                int j0 = 2 * c + t, j1 = 2 * c + 5 - t;
                float ar = I0[rr * 136 + j0], br = I0[rr * 136 + j1];
                float ai = I1[rr * 136 + j0], bi = I1[rr * 136 + j1];
                float p = ar + br, m = ar - br, q = ai + bi, n = ai - bi;
                LLr += KLR[t]*p;  LLr -= KLI[t]*q;
                LLi += KLI[t]*p;  LLi += KLR[t]*q;
                LHr += KHR[t]*m;  LHr -= KHI[t]*n;
                LHi += KHI[t]*m;  LHi += KHR[t]*n;
                ar = I2[rr * 136 + j0]; br = I2[rr * 136 + j1];
                ai = I3[rr * 136 + j0]; bi = I3[rr * 136 + j1];
                p = ar + br; m = ar - br; q = ai + bi; n = ai - bi;
                HLr += KLR[t]*p;  HLr -= KLI[t]*q;
                HLi += KLI[t]*p;  HLi += KLR[t]*q;
                HHr += KHR[t]*m;  HHr -= KHI[t]*n;
                HHi += KHI[t]*m;  HHi += KHR[t]*n;
            }
            o_re[r * 1024 + c + half]          = LHr;
            o_im[r * 1024 + c + half]          = LHi;
            o_re[(r + half) * 1024 + c]        = HLr;
            o_im[(r + half) * 1024 + c]        = HLi;
            o_re[(r + half) * 1024 + c + half] = HHr;
            o_im[(r + half) * 1024 + c + half] = HHi;
            if (last) {
                o_re[r * 1024 + c] = LLr;
                o_im[r * 1024 + c] = LLi;
            } else {
                dre[r * pd + c] = LLr;
                dim[r * pd + c] = LLi;
            }
        }
        __syncthreads();
    }
}

__device__ __forceinline__ void tail_unit(int img, const float* __restrict__ s34,
                                          float* __restrict__ out, float* sm, int tid)
{
    constexpr int AP = 68, BP = 36;
    float* A_re = sm;
    float* A_im = A_re + 64 * AP;
    float* B_re = A_im + 64 * AP;
    float* B_im = B_re + 32 * BP;
    float* I0   = B_im + 32 * BP;
    float* I1   = I0 + 8 * 136;
    float* I2   = I1 + 8 * 136;
    float* I3   = I2 + 8 * 136;

    const float* g_re = s34 + (long)img * 2l * 64 * 64;
    const float* g_im = g_re + 64 * 64;
    for (int idx = tid; idx < 64 * 16; idx += 512) {
        int rr = idx >> 4, c4 = (idx & 15) * 4;
        *(float4*)&A_re[rr * AP + c4] = __ldcg((const float4*)(g_re + rr * 64 + c4));
        *(float4*)&A_im[rr * AP + c4] = __ldcg((const float4*)(g_im + rr * 64 + c4));
    }
    __syncthreads();

    float* o_re = out + (long)img * 2l * 1024 * 1024;
    float* o_im = o_re + 1024 * 1024;

    tail_level(A_re, A_im, AP, B_re, B_im, BP, I0, I1, I2, I3,
               o_re, o_im, 64, false, tid);
    tail_level(B_re, B_im, BP, nullptr, nullptr, 0, I0, I1, I2, I3,
               o_re, o_im, 32, true, tid);
}

// ------------------------------ persistent kernel ---------------------------
__global__ void __launch_bounds__(512, 2)
persist(const float* __restrict__ images, float* __restrict__ out,
        float* __restrict__ s01, float* __restrict__ s12,
        float* __restrict__ s23, float* __restrict__ s34)
{
    extern __shared__ float sm[];
    float* S0 = sm;
    float* S1 = sm + SARR;
    float* S2 = sm + 2 * SARR;
    float* S3 = sm + 3 * SARR;

    const int tid = threadIdx.x;
    const unsigned NB = gridDim.x;

    // L0: 6144 tiles (h=1024, imag = 0, streaming input)
    for (int u = blockIdx.x; u < 6144; u += NB)
        wave_tile<1024, false, true>(u, images, out, s01, S0, S1, S2, S3, tid);
    grid_barrier(NB);
    // L1: 1536 tiles
    for (int u = blockIdx.x; u < 1536; u += NB)
        wave_tile<512, true, false>(u, s01, out, s12, S0, S1, S2, S3, tid);
    grid_barrier(NB);
    // L2: 384 tiles
    for (int u = blockIdx.x; u < 384; u += NB)
        wave_tile<256, true, false>(u, s12, out, s23, S0, S1, S2, S3, tid);
    grid_barrier(NB);
    // L3: 96 tiles
    for (int u = blockIdx.x; u < 96; u += NB)
        wave_tile<128, true, false>(u, s23, out, s34, S0, S1, S2, S3, tid);
    grid_barrier(NB);
    // L4..L5 fused: 24 units
    for (int u = blockIdx.x; u < 24; u += NB)
        tail_unit(u, s34, out, sm, tid);
}

// ================================= launch ===================================
extern "C" void kernel_launch(void* const* d_in, const int* in_sizes, int n_in,
                              void* d_out, int out_size) {
    const float* images = (const float*)d_in[0];
    float* out = (float*)d_out;

    float *s01, *s12, *s23, *s34;
    cudaGetSymbolAddress((void**)&s01, g_s01);
    cudaGetSymbolAddress((void**)&s12, g_s12);
    cudaGetSymbolAddress((void**)&s23, g_s23);
    cudaGetSymbolAddress((void**)&s34, g_s34);

    constexpr size_t SMEM = 15360u * 4u;   // 61,440 B (tail layout; wave uses 39KB)
    cudaFuncSetAttribute(persist, cudaFuncAttributeMaxDynamicSharedMemorySize, SMEM);

    int dev = 0;
    cudaGetDevice(&dev);
    int nsm = 148;
    cudaDeviceGetAttribute(&nsm, cudaDevAttrMultiProcessorCount, dev);
    int occ = 1;
    cudaOccupancyMaxActiveBlocksPerMultiprocessor(&occ, persist, 512, SMEM);
    if (occ < 1) occ = 1;
    if (occ > 2) occ = 2;
    int nb = nsm * occ;

    persist<<<nb, 512, SMEM>>>(images, out, s01, s12, s23, s34);
}

// round 11
// speedup vs baseline: 1.6930x; 1.1042x over previous
#include <cuda_runtime.h>

// ----------------------------------------------------------------------------
// Complex Daubechies wavelet forward decomposition, 6 levels. Round 11:
//  - R8 5-launch chain (best so far) with:
//    * __launch_bounds__(256, 5): 51-reg cap -> 5 blocks/SM (was 4)
//    * L0 phase-A items widened to 8 intermediate cols (24-col x window,
//      two 4-col halves): half the items, 25% less LDG halo traffic
//  - FFMA-immediate coefficients, W-conv in regs -> smem -> H-conv,
//    details via __stcs, LL scratch L2-resident, L0 input via __ldcs.
// ----------------------------------------------------------------------------

#define C_LR0 (-0.046875f)
#define C_LR1 ( 0.078125f)
#define C_LR2 ( 0.46875f)
#define C_LI0 (-0.0605153648f)
#define C_LI1 (-0.0605153648f)
#define C_LI2 ( 0.1210307296f)
#define C_HR0 (-0.046875f)
#define C_HR1 (-0.078125f)
#define C_HR2 ( 0.46875f)
#define C_HI0 ( 0.0605153648f)
#define C_HI1 (-0.0605153648f)
#define C_HI2 (-0.1210307296f)

#define DECL_COEFS \
    const float KLR[3] = {C_LR0, C_LR1, C_LR2}; \
    const float KLI[3] = {C_LI0, C_LI1, C_LI2}; \
    const float KHR[3] = {C_HR0, C_HR1, C_HR2}; \
    const float KHI[3] = {C_HI0, C_HI1, C_HI2};

// Ping-pong scratch for the LL chain.
__device__ float g_scr0[32u * 2u * 512u * 512u];
__device__ float g_scr1[32u * 2u * 512u * 512u];

// Tile constants: TR=16, TC=32, 36 intermediate rows, pitch 36.
#define TRW 16
#define TCW 32
#define RIW 36
#define PW  36

// --------- shared phase-B body (H-direction conv -> 4 quadrants) -----------
template<int H>
__device__ __forceinline__ void phaseB(
    const float* S0, const float* S1, const float* S2, const float* S3,
    float* __restrict__ out, float* __restrict__ nxt,
    int img, int r0, int c0, int tid)
{
    DECL_COEFS
    constexpr int half = H / 2;
    float* o_re = out + (long)img * (2l * 1024 * 1024);
    float* o_im = o_re + 1024 * 1024;
    float* n_re = nxt + (long)img * 2l * half * half;
    float* n_im = n_re + (long)half * half;

    int r  = tid >> 4;          // 16 rows x 16 col-groups = 256 items exactly
    int cg = tid & 15;
    int c2 = 2 * cg;
    float LLr0=0, LLi0=0, LHr0=0, LHi0=0, HLr0=0, HLi0=0, HHr0=0, HHi0=0;
    float LLr1=0, LLi1=0, LHr1=0, LHi1=0, HLr1=0, HLi1=0, HHr1=0, HHi1=0;
    #pragma unroll
    for (int t = 0; t < 3; t++) {
        int ra = (2 * r + t) * PW + c2;
        int rb = (2 * r + 5 - t) * PW + c2;
        float2 art = *(const float2*)&S0[ra], ars = *(const float2*)&S0[rb];
        float2 ait = *(const float2*)&S1[ra], ais = *(const float2*)&S1[rb];
        float2 brt = *(const float2*)&S2[ra], brs = *(const float2*)&S2[rb];
        float2 bit = *(const float2*)&S3[ra], bis = *(const float2*)&S3[rb];
        {
            float p = art.x + ars.x, m = art.x - ars.x;
            float q = ait.x + ais.x, n = ait.x - ais.x;
            LLr0 += KLR[t]*p;  LLr0 -= KLI[t]*q;
            LLi0 += KLI[t]*p;  LLi0 += KLR[t]*q;
            HLr0 += KHR[t]*m;  HLr0 -= KHI[t]*n;
            HLi0 += KHI[t]*m;  HLi0 += KHR[t]*n;
            float p2 = brt.x + brs.x, m2 = brt.x - brs.x;
            float q2 = bit.x + bis.x, n2 = bit.x - bis.x;
            LHr0 += KLR[t]*p2; LHr0 -= KLI[t]*q2;
            LHi0 += KLI[t]*p2; LHi0 += KLR[t]*q2;
            HHr0 += KHR[t]*m2; HHr0 -= KHI[t]*n2;
            HHi0 += KHI[t]*m2; HHi0 += KHR[t]*n2;
        }
        {
            float p = art.y + ars.y, m = art.y - ars.y;
            float q = ait.y + ais.y, n = ait.y - ais.y;
            LLr1 += KLR[t]*p;  LLr1 -= KLI[t]*q;
            LLi1 += KLI[t]*p;  LLi1 += KLR[t]*q;
            HLr1 += KHR[t]*m;  HLr1 -= KHI[t]*n;
            HLi1 += KHI[t]*m;  HLi1 += KHR[t]*n;
            float p2 = brt.y + brs.y, m2 = brt.y - brs.y;
            float q2 = bit.y + bis.y, n2 = bit.y - bis.y;
            LHr1 += KLR[t]*p2; LHr1 -= KLI[t]*q2;
            LHi1 += KLI[t]*p2; LHi1 += KLR[t]*q2;
            HHr1 += KHR[t]*m2; HHr1 -= KHI[t]*n2;
            HHi1 += KHI[t]*m2; HHi1 += KHR[t]*n2;
        }
    }
    int rl = r0 + r, rh = rl + half;
    int cl = c0 + c2, ch = cl + half;
    *(float2*)(n_re + (long)rl * half + cl) = make_float2(LLr0, LLr1);
    *(float2*)(n_im + (long)rl * half + cl) = make_float2(LLi0, LLi1);
    __stcs((float2*)(o_re + (long)rl * 1024 + ch), make_float2(LHr0, LHr1));
    __stcs((float2*)(o_im + (long)rl * 1024 + ch), make_float2(LHi0, LHi1));
    __stcs((float2*)(o_re + (long)rh * 1024 + cl), make_float2(HLr0, HLr1));
    __stcs((float2*)(o_im + (long)rh * 1024 + cl), make_float2(HLi0, HLi1));
    __stcs((float2*)(o_re + (long)rh * 1024 + ch), make_float2(HHr0, HHr1));
    __stcs((float2*)(o_im + (long)rh * 1024 + ch), make_float2(HHi0, HHi1));
}

// ======================= level-0 kernel (no imag input) =====================
__global__ void __launch_bounds__(256, 5)
wave0(const float* __restrict__ in, float* __restrict__ out,
      float* __restrict__ nxt)
{
    DECL_COEFS
    constexpr int H = 1024, hm = H - 1;
    __shared__ __align__(16) float S0[RIW * PW];
    __shared__ __align__(16) float S1[RIW * PW];
    __shared__ __align__(16) float S2[RIW * PW];
    __shared__ __align__(16) float S3[RIW * PW];

    const int tid = threadIdx.x;
    const int img = blockIdx.z;
    const int r0  = blockIdx.y * TRW;
    const int c0  = blockIdx.x * TCW;

    const float* in_re = in + (long)img * (1024l * 1024);

    // ---- Phase A: 8 intermediate cols per item (two 4-col halves) ----------
    const int gr0  = 2 * r0 - 3;
    const int gcal = 2 * c0 - 4;
    for (int idx = tid; idx < RIW * (TCW / 8); idx += 256) {   // 144 items
        int ri = idx >> 2;
        int j  = idx & 3;
        int gr = (gr0 + ri) & hm;
        const float* pr = in_re + (long)gr * H;
        float x[24];
        #pragma unroll
        for (int k = 0; k < 6; k++) {
            int gc = (gcal + 16 * j + 4 * k) & hm;
            float4 v = __ldcs((const float4*)(pr + gc));
            x[4*k] = v.x; x[4*k+1] = v.y; x[4*k+2] = v.z; x[4*k+3] = v.w;
        }
        int o = ri * PW + 8 * j;
        #pragma unroll
        for (int hh = 0; hh < 2; hh++) {
            float lre[4], lim[4], hre[4], him[4];
            #pragma unroll
            for (int c = 0; c < 4; c++) {
                int cc = c + 4 * hh;
                float a = 0.f, b = 0.f, d = 0.f, e = 0.f;
                #pragma unroll
                for (int t = 0; t < 3; t++) {
                    float xt = x[2*cc + 1 + t], xs = x[2*cc + 6 - t];
                    float p = xt + xs, m = xt - xs;
                    a += KLR[t] * p;  b += KLI[t] * p;
                    d += KHR[t] * m;  e += KHI[t] * m;
                }
                lre[c] = a; lim[c] = b; hre[c] = d; him[c] = e;
            }
            int oo = o + 4 * hh;
            *(float4*)&S0[oo] = make_float4(lre[0], lre[1], lre[2], lre[3]);
            *(float4*)&S1[oo] = make_float4(lim[0], lim[1], lim[2], lim[3]);
            *(float4*)&S2[oo] = make_float4(hre[0], hre[1], hre[2], hre[3]);
            *(float4*)&S3[oo] = make_float4(him[0], him[1], him[2], him[3]);
        }
    }
    __syncthreads();
    phaseB<1024>(S0, S1, S2, S3, out, nxt, img, r0, c0, tid);
}

// ===================== levels 1..3 kernel (complex input) ===================
template<int H>
__global__ void __launch_bounds__(256, 5)
wave(const float* __restrict__ in, float* __restrict__ out,
     float* __restrict__ nxt)
{
    DECL_COEFS
    constexpr int hm = H - 1;
    __shared__ __align__(16) float S0[RIW * PW];
    __shared__ __align__(16) float S1[RIW * PW];
    __shared__ __align__(16) float S2[RIW * PW];
    __shared__ __align__(16) float S3[RIW * PW];

    const int tid = threadIdx.x;
    const int img = blockIdx.z;
    const int r0  = blockIdx.y * TRW;
    const int c0  = blockIdx.x * TCW;

    const float* in_re = in + (long)img * (2l * H * H);
    const float* in_im = in_re + (long)H * H;

    const int gr0  = 2 * r0 - 3;
    const int gcal = 2 * c0 - 4;
    for (int idx = tid; idx < RIW * (TCW / 4); idx += 256) {   // 288 items
        int ri = idx >> 3;
        int j  = idx & 7;
        int gr = (gr0 + ri) & hm;
        const float* pr = in_re + (long)gr * H;
        const float* pi = in_im + (long)gr * H;
        float x[16], y[16];
        #pragma unroll
        for (int k = 0; k < 4; k++) {
            int gc = (gcal + 8 * j + 4 * k) & hm;
            float4 v = *(const float4*)(pr + gc);
            x[4*k] = v.x; x[4*k+1] = v.y; x[4*k+2] = v.z; x[4*k+3] = v.w;
            float4 w = *(const float4*)(pi + gc);
            y[4*k] = w.x; y[4*k+1] = w.y; y[4*k+2] = w.z; y[4*k+3] = w.w;
        }
        float lre[4], lim[4], hre[4], him[4];
        #pragma unroll
        for (int c = 0; c < 4; c++) {
            float a = 0.f, b = 0.f, d = 0.f, e = 0.f;
            #pragma unroll
            for (int t = 0; t < 3; t++) {
                float xt = x[2*c + 1 + t], xs = x[2*c + 6 - t];
                float p = xt + xs, m = xt - xs;
                a += KLR[t] * p;  b += KLI[t] * p;
                d += KHR[t] * m;  e += KHI[t] * m;
                float yt = y[2*c + 1 + t], ys = y[2*c + 6 - t];
                float q = yt + ys, n = yt - ys;
                a -= KLI[t] * q;  b += KLR[t] * q;
                d -= KHI[t] * n;  e += KHR[t] * n;
            }
            lre[c] = a; lim[c] = b; hre[c] = d; him[c] = e;
        }
        int o = ri * PW + 4 * j;
        *(float4*)&S0[o] = make_float4(lre[0], lre[1], lre[2], lre[3]);
        *(float4*)&S1[o] = make_float4(lim[0], lim[1], lim[2], lim[3]);
        *(float4*)&S2[o] = make_float4(hre[0], hre[1], hre[2], hre[3]);
        *(float4*)&S3[o] = make_float4(him[0], him[1], him[2], him[3]);
    }
    __syncthreads();
    phaseB<H>(S0, S1, S2, S3, out, nxt, img, r0, c0, tid);
}

// =============================== levels 4..5 ================================
__device__ __forceinline__ void tail_level(
    const float* sre, const float* sim, int ps,
    float* dre, float* dim, int pd,
    float* I0, float* I1, float* I2, float* I3,
    float* o_re, float* o_im, int h, bool last, int tid)
{
    DECL_COEFS
    const int hm = h - 1, W = h + 5, half = h >> 1;
    for (int s0 = 0; s0 < half; s0 += 8) {
        for (int idx = tid; idx < 8 * W; idx += 512) {
            int rr = idx / W, jx = idx - rr * W;
            int col = (jx - 3) & hm;
            int r2 = 2 * (s0 + rr) - 3;
            float aLr = 0, aLi = 0, aHr = 0, aHi = 0;
            #pragma unroll
            for (int t = 0; t < 3; t++) {
                int ra = (r2 + t) & hm, rb = (r2 + 5 - t) & hm;
                float xa = sre[ra * ps + col], xb = sre[rb * ps + col];
                float va = sim[ra * ps + col], vb = sim[rb * ps + col];
                float p = xa + xb, m = xa - xb, q = va + vb, n = va - vb;
                aLr += KLR[t]*p;  aLr -= KLI[t]*q;
                aLi += KLI[t]*p;  aLi += KLR[t]*q;
                aHr += KHR[t]*m;  aHr -= KHI[t]*n;
                aHi += KHI[t]*m;  aHi += KHR[t]*n;
            }
            I0[rr * 136 + jx] = aLr; I1[rr * 136 + jx] = aLi;
            I2[rr * 136 + jx] = aHr; I3[rr * 136 + jx] = aHi;
        }
        __syncthreads();
        for (int idx = tid; idx < 8 * half; idx += 512) {
            int rr = idx / half, c = idx - rr * half;
            int r = s0 + rr;
            float LLr = 0, LLi = 0, LHr = 0, LHi = 0;
            float HLr = 0, HLi = 0, HHr = 0, HHi = 0;
            #pragma unroll
            for (int t = 0; t < 3; t++) {
                int j0 = 2 * c + t, j1 = 2 * c + 5 - t;
                float ar = I0[rr * 136 + j0], br = I0[rr * 136 + j1];
                float ai = I1[rr * 136 + j0], bi = I1[rr * 136 + j1];
                float p = ar + br, m = ar - br, q = ai + bi, n = ai - bi;
                LLr += KLR[t]*p;  LLr -= KLI[t]*q;
                LLi += KLI[t]*p;  LLi += KLR[t]*q;
                LHr += KHR[t]*m;  LHr -= KHI[t]*n;
                LHi += KHI[t]*m;  LHi += KHR[t]*n;
                ar = I2[rr * 136 + j0]; br = I2[rr * 136 + j1];
                ai = I3[rr * 136 + j0]; bi = I3[rr * 136 + j1];
                p = ar + br; m = ar - br; q = ai + bi; n = ai - bi;
                HLr += KLR[t]*p;  HLr -= KLI[t]*q;
                HLi += KLI[t]*p;  HLi += KLR[t]*q;
                HHr += KHR[t]*m;  HHr -= KHI[t]*n;
                HHi += KHI[t]*m;  HHi += KHR[t]*n;
            }
            o_re[r * 1024 + c + half]          = LHr;
            o_im[r * 1024 + c + half]          = LHi;
            o_re[(r + half) * 1024 + c]        = HLr;
            o_im[(r + half) * 1024 + c]        = HLi;
            o_re[(r + half) * 1024 + c + half] = HHr;
            o_im[(r + half) * 1024 + c + half] = HHi;
            if (last) {
                o_re[r * 1024 + c] = LLr;
                o_im[r * 1024 + c] = LLi;
            } else {
                dre[r * pd + c] = LLr;
                dim[r * pd + c] = LLi;
            }
        }
        __syncthreads();
    }
}

__global__ void __launch_bounds__(512)
wave_tail45(const float* __restrict__ in, float* __restrict__ out)
{
    extern __shared__ float sm[];
    constexpr int AP = 68, BP = 36;
    float* A_re = sm;
    float* A_im = A_re + 64 * AP;
    float* B_re = A_im + 64 * AP;
    float* B_im = B_re + 32 * BP;
    float* I0   = B_im + 32 * BP;
    float* I1   = I0 + 8 * 136;
    float* I2   = I1 + 8 * 136;
    float* I3   = I2 + 8 * 136;

    const int tid = threadIdx.x;
    const int img = blockIdx.x;

    const float* g_re = in + (long)img * 2l * 64 * 64;
    const float* g_im = g_re + 64 * 64;
    for (int idx = tid; idx < 64 * 16; idx += 512) {
        int rr = idx >> 4, c4 = (idx & 15) * 4;
        *(float4*)&A_re[rr * AP + c4] = *(const float4*)(g_re + rr * 64 + c4);
        *(float4*)&A_im[rr * AP + c4] = *(const float4*)(g_im + rr * 64 + c4);
    }
    __syncthreads();

    float* o_re = out + (long)img * 2l * 1024 * 1024;
    float* o_im = o_re + 1024 * 1024;

    tail_level(A_re, A_im, AP, B_re, B_im, BP, I0, I1, I2, I3,
               o_re, o_im, 64, false, tid);
    tail_level(B_re, B_im, BP, nullptr, nullptr, 0, I0, I1, I2, I3,
               o_re, o_im, 32, true, tid);
}

// ================================= launch ===================================
extern "C" void kernel_launch(void* const* d_in, const int* in_sizes, int n_in,
                              void* d_out, int out_size) {
    const float* images = (const float*)d_in[0];
    float* out = (float*)d_out;

    float *scr0 = nullptr, *scr1 = nullptr;
    cudaGetSymbolAddress((void**)&scr0, g_scr0);
    cudaGetSymbolAddress((void**)&scr1, g_scr1);

    const int bc = in_sizes[0] / (1024 * 1024);  // B*C = 24

    constexpr size_t SMT = (size_t)(2 * 64 * 68 + 2 * 32 * 36 + 4 * 8 * 136) * 4;
    cudaFuncSetAttribute(wave_tail45,
                         cudaFuncAttributeMaxDynamicSharedMemorySize, SMT);

    dim3 blk(256);
    // Level 0: h=1024 (imag identically zero), widened phase-A items
    {
        dim3 grid(512 / 32, 512 / 16, bc);
        wave0<<<grid, blk>>>(images, out, scr0);
    }
    // Level 1: h=512
    {
        dim3 grid(256 / 32, 256 / 16, bc);
        wave<512><<<grid, blk>>>(scr0, out, scr1);
    }
    // Level 2: h=256
    {
        dim3 grid(128 / 32, 128 / 16, bc);
        wave<256><<<grid, blk>>>(scr1, out, scr0);
    }
    // Level 3: h=128
    {
        dim3 grid(64 / 32, 64 / 16, bc);
        wave<128><<<grid, blk>>>(scr0, out, scr1);
    }
    // Levels 4..5 fused, one block per image
    wave_tail45<<<bc, 512, SMT>>>(scr1, out);
}